// round 12
// baseline (speedup 1.0000x reference)
#include <cuda_runtime.h>
#include <cstdint>

#define T_STEPS 2048
#define BATCH   64
#define IDIM    512
#define HDIM    512

#define N_GROUPS 16           // chains of 4 batch rows
#define BLKS_PER_GROUP 16     // column blocks per chain (32 H-cols each)
#define B_PER_GROUP 4
#define COLS_PER_BLK 32

typedef unsigned long long u64;

// ---------------- scratch -----------------------------------------------
__device__ float g_xf[(long)T_STEPS * BATCH * HDIM];
__device__ float g_xh[(long)T_STEPS * BATCH * HDIM];
__device__ float g_hbuf[BATCH * HDIM];
__device__ float g_gbuf[BATCH * HDIM];
// packed flags: chain c -> u16[ c*64 + 0..15 ] = phase A (one per block),
//               u16[ c*64 + 32..47 ] = phase B. 128B stride per chain.
__device__ __align__(16) unsigned short g_flags[N_GROUPS * 64];

// ---------------- packed f32x2 helpers -----------------------------------
__device__ __forceinline__ u64 pack2(float x, float y) {
    u64 r; asm("mov.b64 %0, {%1, %2};" : "=l"(r) : "f"(x), "f"(y)); return r;
}
__device__ __forceinline__ u64 ffma2(u64 a, u64 b, u64 c) {
    u64 d; asm("fma.rn.f32x2 %0, %1, %2, %3;" : "=l"(d) : "l"(a), "l"(b), "l"(c));
    return d;
}
__device__ __forceinline__ float2 unpack2(u64 a) {
    float2 r; asm("mov.b64 {%0, %1}, %2;" : "=f"(r.x), "=f"(r.y) : "l"(a)); return r;
}
__device__ __forceinline__ float4 ldcg4(const float4* p) {
    float4 v;
    asm volatile("ld.global.cg.v4.f32 {%0,%1,%2,%3}, [%4];"
                 : "=f"(v.x), "=f"(v.y), "=f"(v.z), "=f"(v.w) : "l"(p));
    return v;
}
__device__ __forceinline__ void st_release_u16(unsigned short* p, unsigned short v) {
    asm volatile("st.release.gpu.global.u16 [%0], %1;" :: "l"(p), "h"(v) : "memory");
}
__device__ __forceinline__ u64 ld_acq64(const u64* p) {
    u64 v;
    asm volatile("ld.acquire.gpu.global.u64 %0, [%1];" : "=l"(v) : "l"(p) : "memory");
    return v;
}
__device__ __forceinline__ float sigmoid_f(float x) {
    return __fdividef(1.0f, 1.0f + __expf(-x));
}
__device__ __forceinline__ float tanh_ap(float x) {
    float y; asm("tanh.approx.f32 %0, %1;" : "=f"(y) : "f"(x)); return y;
}

// wait until all 16 block-flags equal val. LANE 0 ONLY polls (4x u64
// acquire loads cover the whole 32B flag word); __syncwarp broadcasts
// the acquired visibility (same proven pattern as the R7 champion).
__device__ __forceinline__ void flag_wait16(const unsigned short* f,
                                            unsigned int val, int j)
{
    if (j == 0) {
        const u64* p = (const u64*)f;
        const u64 e = 0x0001000100010001ULL * (u64)val;
        for (;;) {
            u64 a = ld_acq64(p);
            u64 b = ld_acq64(p + 1);
            u64 c = ld_acq64(p + 2);
            u64 d = ld_acq64(p + 3);
            if (a == e && b == e && c == e && d == e) break;
        }
    }
    __syncwarp();
}

// ============================================================================
// Phase 1: input projections. Block (0,0,0) zeroes flags; blocks (x<16,0,0)
// seed g_hbuf from h0. Re-done every launch (graph-replay safe).
// ============================================================================
__global__ __launch_bounds__(256) void proj_kernel(
    const float* __restrict__ X,  const float* __restrict__ h0,
    const float* __restrict__ Wf, const float* __restrict__ bf,
    const float* __restrict__ Wh, const float* __restrict__ bh)
{
    if (blockIdx.y == 0 && blockIdx.z == 0) {
        if (blockIdx.x == 0) {
            unsigned int* fl = (unsigned int*)g_flags;   // 512 u32
            fl[threadIdx.x]       = 0u;
            fl[threadIdx.x + 256] = 0u;
        }
        if (blockIdx.x < 16) {
            const float4* s = (const float4*)&h0[blockIdx.x * 4 * HDIM];
            float4* d = (float4*)&g_hbuf[blockIdx.x * 4 * HDIM];
            d[threadIdx.x]       = s[threadIdx.x];
            d[threadIdx.x + 256] = s[threadIdx.x + 256];
        }
    }

    const float* W  = blockIdx.z ? Wh : Wf;
    const float* bv = blockIdx.z ? bh : bf;
    float* out = blockIdx.z ? g_xh : g_xf;

    __shared__ float As[16][132];
    __shared__ float Bs[16][68];

    const int tid = threadIdx.x;
    const int tx = tid & 15;
    const int ty = tid >> 4;
    const long m0 = (long)blockIdx.x * 128;
    const int  n0 = blockIdx.y * 64;

    u64 acc[4][4];
    #pragma unroll
    for (int p = 0; p < 4; p++)
        #pragma unroll
        for (int c = 0; c < 4; c++) acc[p][c] = 0ull;

    for (int k0 = 0; k0 < IDIM; k0 += 16) {
        #pragma unroll
        for (int q0 = 0; q0 < 2; q0++) {
            int q = tid + q0 * 256;
            int row = q >> 2;
            int kc  = (q & 3) * 4;
            float4 v = *(const float4*)&X[(m0 + row) * IDIM + k0 + kc];
            As[kc+0][row] = v.x; As[kc+1][row] = v.y;
            As[kc+2][row] = v.z; As[kc+3][row] = v.w;
        }
        {
            int row = tid >> 2;
            int kc  = (tid & 3) * 4;
            float4 v = *(const float4*)&W[(n0 + row) * IDIM + k0 + kc];
            Bs[kc+0][row] = v.x; Bs[kc+1][row] = v.y;
            Bs[kc+2][row] = v.z; Bs[kc+3][row] = v.w;
        }
        __syncthreads();

        #pragma unroll
        for (int kk = 0; kk < 16; kk++) {
            float4 a0 = *(const float4*)&As[kk][ty * 8];
            float4 a1 = *(const float4*)&As[kk][ty * 8 + 4];
            float4 b4 = *(const float4*)&Bs[kk][tx * 4];
            u64 a2[4] = { pack2(a0.x, a0.y), pack2(a0.z, a0.w),
                          pack2(a1.x, a1.y), pack2(a1.z, a1.w) };
            u64 bb[4] = { pack2(b4.x, b4.x), pack2(b4.y, b4.y),
                          pack2(b4.z, b4.z), pack2(b4.w, b4.w) };
            #pragma unroll
            for (int p = 0; p < 4; p++)
                #pragma unroll
                for (int c = 0; c < 4; c++)
                    acc[p][c] = ffma2(a2[p], bb[c], acc[p][c]);
        }
        __syncthreads();
    }

    float4 bias4 = *(const float4*)&bv[n0 + tx * 4];
    #pragma unroll
    for (int p = 0; p < 4; p++) {
        float2 c0 = unpack2(acc[p][0]);
        float2 c1 = unpack2(acc[p][1]);
        float2 c2 = unpack2(acc[p][2]);
        float2 c3 = unpack2(acc[p][3]);
        long mlo = m0 + ty * 8 + 2 * p;
        float4 lo = make_float4(c0.x + bias4.x, c1.x + bias4.y,
                                c2.x + bias4.z, c3.x + bias4.w);
        float4 hi = make_float4(c0.y + bias4.x, c1.y + bias4.y,
                                c2.y + bias4.z, c3.y + bias4.w);
        *(float4*)&out[mlo * HDIM + n0 + tx * 4]       = lo;
        *(float4*)&out[(mlo + 1) * HDIM + n0 + tx * 4] = hi;
    }
}

// ============================================================================
// Phase 2: persistent scan (R7 champion body; packed-flag sync, no atomics).
// 256 blocks x 128 threads, 2/SM. Chain = 4 batch rows x 16 column blocks.
// Warp w owns k-slice [w*128,+128) + finalize row w. Wf register-resident;
// Wh in conflict-free SMEM slices. Release = __syncthreads + ONE u16
// release-store per block; wait = lane-0 poll of the packed 32B flag word.
// ============================================================================
#define WH_STRIDE 132
#define SCAN_SMEM ((128 * WH_STRIDE + 4 * 512 + 512 + 512) * 4)

__global__ void __launch_bounds__(128, 2) scan_kernel(
    const float* __restrict__ h0,
    const float* __restrict__ Whf,
    const float* __restrict__ Whh,
    float* __restrict__ out)
{
    extern __shared__ float smem[];
    float* whs   = smem;                     // 128 slices x 132
    float* srcs  = whs + 128 * WH_STRIDE;    // 4 warps x 512 (warp-private)
    float* partA = srcs + 4 * 512;           // [row][ks][j] 4*4*32
    float* partB = partA + 512;

    const int tid = threadIdx.x;
    const int j   = tid & 31;      // lane = column within block
    const int w   = tid >> 5;      // warp = k-slice index AND finalize row
    const int grp = blockIdx.x >> 4;
    const int blk = blockIdx.x & 15;
    const int j0  = blk * COLS_PER_BLK;
    const int b0  = grp * B_PER_GROUP;
    const int kb  = w * 128;

    unsigned short* flagA = &g_flags[grp * 64];
    unsigned short* flagB = &g_flags[grp * 64 + 32];

    // Wf slice -> registers (128 floats = 64 u64)
    u64 wf2[64];
    #pragma unroll
    for (int i = 0; i < 32; i++) {
        float4 v = *(const float4*)&Whf[(j0 + j) * HDIM + kb + 4 * i];
        wf2[2*i] = pack2(v.x, v.y); wf2[2*i+1] = pack2(v.z, v.w);
    }
    // Wh slice -> private SMEM region (thread-local)
    float* wr = &whs[(w * 32 + j) * WH_STRIDE];
    #pragma unroll
    for (int i = 0; i < 32; i++)
        *(float4*)&wr[4 * i] = *(const float4*)&Whh[(j0 + j) * HDIM + kb + 4 * i];

    float hp = h0[(b0 + w) * HDIM + j0 + j];
    __syncthreads();

    float* sb = &srcs[w * 512];
    const long xstep = (long)BATCH * HDIM;
    long xoff = (long)(b0 + w) * HDIM + j0 + j;   // rolling [t,b,col] offset

    float f_reg = 0.0f;

    for (int t = 0; t < T_STEPS; t++) {
        const unsigned int tcur = (unsigned int)(t + 1);
        const float xf_v = __ldcs(&g_xf[xoff]);
        const float xh_v = __ldcs(&g_xh[xoff]);

        // ---- wait for h_{t-1} (all 16 blocks' B-flag == t) ----
        if (t > 0) flag_wait16(flagB, tcur - 1u, j);

        // ---- per-warp gather: 4 rows x own k-slice of h ----
        {
            const float4* hb = (const float4*)&g_hbuf[b0 * HDIM + kb];
            float4 v0 = ldcg4(hb + j);
            float4 v1 = ldcg4(hb + 128 + j);
            float4 v2 = ldcg4(hb + 256 + j);
            float4 v3 = ldcg4(hb + 384 + j);
            *(float4*)&sb[        4 * j] = v0;
            *(float4*)&sb[128 +   4 * j] = v1;
            *(float4*)&sb[256 +   4 * j] = v2;
            *(float4*)&sb[384 +   4 * j] = v3;
        }
        __syncwarp();

        // ---- GEMM A (f gate), Wf from registers ----
        {
            u64 a0 = 0ull, a1 = 0ull, a2 = 0ull, a3 = 0ull;
            #pragma unroll
            for (int i = 0; i < 32; i++) {
                u64 wlo = wf2[2*i], whi = wf2[2*i+1];
                float4 x0 = *(const float4*)&sb[        4 * i];
                float4 x1 = *(const float4*)&sb[128 +   4 * i];
                float4 x2 = *(const float4*)&sb[256 +   4 * i];
                float4 x3 = *(const float4*)&sb[384 +   4 * i];
                a0 = ffma2(wlo, pack2(x0.x, x0.y), a0);
                a0 = ffma2(whi, pack2(x0.z, x0.w), a0);
                a1 = ffma2(wlo, pack2(x1.x, x1.y), a1);
                a1 = ffma2(whi, pack2(x1.z, x1.w), a1);
                a2 = ffma2(wlo, pack2(x2.x, x2.y), a2);
                a2 = ffma2(whi, pack2(x2.z, x2.w), a2);
                a3 = ffma2(wlo, pack2(x3.x, x3.y), a3);
                a3 = ffma2(whi, pack2(x3.z, x3.w), a3);
            }
            float2 r0 = unpack2(a0), r1 = unpack2(a1);
            float2 r2 = unpack2(a2), r3 = unpack2(a3);
            partA[(0 * 4 + w) * 32 + j] = r0.x + r0.y;
            partA[(1 * 4 + w) * 32 + j] = r1.x + r1.y;
            partA[(2 * 4 + w) * 32 + j] = r2.x + r2.y;
            partA[(3 * 4 + w) * 32 + j] = r3.x + r3.y;
        }
        __syncthreads();

        // ---- finalize A: warp w owns row w; publish g ----
        {
            float s = xf_v;
            #pragma unroll
            for (int q = 0; q < 4; q++) s += partA[(w * 4 + q) * 32 + j];
            f_reg = sigmoid_f(s);
            g_gbuf[(b0 + w) * HDIM + j0 + j] = f_reg * hp;
        }
        __syncthreads();                       // all g stores of the block done
        if (tid == 0) st_release_u16(&flagA[blk], (unsigned short)tcur);

        // ---- wait for g_t (all 16 blocks' A-flag == t+1) ----
        flag_wait16(flagA, tcur, j);

        // ---- per-warp gather of g ----
        {
            const float4* gb = (const float4*)&g_gbuf[b0 * HDIM + kb];
            float4 v0 = ldcg4(gb + j);
            float4 v1 = ldcg4(gb + 128 + j);
            float4 v2 = ldcg4(gb + 256 + j);
            float4 v3 = ldcg4(gb + 384 + j);
            *(float4*)&sb[        4 * j] = v0;
            *(float4*)&sb[128 +   4 * j] = v1;
            *(float4*)&sb[256 +   4 * j] = v2;
            *(float4*)&sb[384 +   4 * j] = v3;
        }
        __syncwarp();

        // ---- GEMM B (candidate), Wh from SMEM ----
        {
            u64 a0 = 0ull, a1 = 0ull, a2 = 0ull, a3 = 0ull;
            #pragma unroll
            for (int i = 0; i < 32; i++) {
                float4 wv = *(const float4*)&wr[4 * i];
                u64 wlo = pack2(wv.x, wv.y), whi = pack2(wv.z, wv.w);
                float4 x0 = *(const float4*)&sb[        4 * i];
                float4 x1 = *(const float4*)&sb[128 +   4 * i];
                float4 x2 = *(const float4*)&sb[256 +   4 * i];
                float4 x3 = *(const float4*)&sb[384 +   4 * i];
                a0 = ffma2(wlo, pack2(x0.x, x0.y), a0);
                a0 = ffma2(whi, pack2(x0.z, x0.w), a0);
                a1 = ffma2(wlo, pack2(x1.x, x1.y), a1);
                a1 = ffma2(whi, pack2(x1.z, x1.w), a1);
                a2 = ffma2(wlo, pack2(x2.x, x2.y), a2);
                a2 = ffma2(whi, pack2(x2.z, x2.w), a2);
                a3 = ffma2(wlo, pack2(x3.x, x3.y), a3);
                a3 = ffma2(whi, pack2(x3.z, x3.w), a3);
            }
            float2 r0 = unpack2(a0), r1 = unpack2(a1);
            float2 r2 = unpack2(a2), r3 = unpack2(a3);
            partB[(0 * 4 + w) * 32 + j] = r0.x + r0.y;
            partB[(1 * 4 + w) * 32 + j] = r1.x + r1.y;
            partB[(2 * 4 + w) * 32 + j] = r2.x + r2.y;
            partB[(3 * 4 + w) * 32 + j] = r3.x + r3.y;
        }
        __syncthreads();

        // ---- finalize B: blend, emit y and h ----
        {
            float s = xh_v;
            #pragma unroll
            for (int q = 0; q < 4; q++) s += partB[(w * 4 + q) * 32 + j];
            float ht = tanh_ap(s);
            float hn = fmaf(f_reg, ht - hp, hp);        // (1-f)h + f*ht
            __stcs(&out[xoff], hn);
            g_hbuf[(b0 + w) * HDIM + j0 + j] = hn;
            if (t == T_STEPS - 1)
                out[(long)T_STEPS * xstep + (b0 + w) * HDIM + j0 + j] = hn;
            hp = hn;
        }
        __syncthreads();                       // all h stores of the block done
        if (tid == 0) st_release_u16(&flagB[blk], (unsigned short)tcur);

        xoff += xstep;
    }
}

// ============================================================================
extern "C" void kernel_launch(void* const* d_in, const int* in_sizes, int n_in,
                              void* d_out, int out_size)
{
    const float* x   = (const float*)d_in[0];
    const float* h0  = (const float*)d_in[1];
    const float* Wxf = (const float*)d_in[2];
    const float* Whf = (const float*)d_in[3];
    const float* bf  = (const float*)d_in[4];
    const float* Wxh = (const float*)d_in[5];
    const float* Whh = (const float*)d_in[6];
    const float* bh  = (const float*)d_in[7];
    float* out = (float*)d_out;

    cudaFuncSetAttribute(scan_kernel,
                         cudaFuncAttributeMaxDynamicSharedMemorySize, SCAN_SMEM);

    dim3 pgrid((T_STEPS * BATCH) / 128, HDIM / 64, 2);
    proj_kernel<<<pgrid, 256>>>(x, h0, Wxf, bf, Wxh, bh);

    scan_kernel<<<N_GROUPS * BLKS_PER_GROUP, 128, SCAN_SMEM>>>(h0, Whf, Whh, out);
}

// round 13
// speedup vs baseline: 2.1085x; 2.1085x over previous
#include <cuda_runtime.h>
#include <cstdint>

#define T_STEPS 2048
#define BATCH   64
#define IDIM    512
#define HDIM    512

#define N_GROUPS 16           // chains of 4 batch rows
#define BLKS_PER_GROUP 16     // column blocks per chain (32 H-cols each)
#define B_PER_GROUP 4
#define COLS_PER_BLK 32

typedef unsigned long long u64;

// ---------------- scratch -----------------------------------------------
__device__ float g_xf[(long)T_STEPS * BATCH * HDIM];
__device__ float g_xh[(long)T_STEPS * BATCH * HDIM];
__device__ float g_hbuf[BATCH * HDIM];
__device__ float g_gbuf[BATCH * HDIM];
// per-block atomic flags, ONE PER 128B LINE (32 u32 stride).
// line index = grp*32 + phase*16 + blk   (phase 0 = A/g, 1 = B/h)
__device__ unsigned int g_flg[N_GROUPS * 32 * 32];

// ---------------- packed f32x2 helpers -----------------------------------
__device__ __forceinline__ u64 pack2(float x, float y) {
    u64 r; asm("mov.b64 %0, {%1, %2};" : "=l"(r) : "f"(x), "f"(y)); return r;
}
__device__ __forceinline__ u64 ffma2(u64 a, u64 b, u64 c) {
    u64 d; asm("fma.rn.f32x2 %0, %1, %2, %3;" : "=l"(d) : "l"(a), "l"(b), "l"(c));
    return d;
}
__device__ __forceinline__ float2 unpack2(u64 a) {
    float2 r; asm("mov.b64 {%0, %1}, %2;" : "=f"(r.x), "=f"(r.y) : "l"(a)); return r;
}
__device__ __forceinline__ float4 ldcg4(const float4* p) {
    float4 v;
    asm volatile("ld.global.cg.v4.f32 {%0,%1,%2,%3}, [%4];"
                 : "=f"(v.x), "=f"(v.y), "=f"(v.z), "=f"(v.w) : "l"(p));
    return v;
}
__device__ __forceinline__ void red_release(unsigned int* p) {
    asm volatile("red.release.gpu.global.add.u32 [%0], 1;" :: "l"(p) : "memory");
}
__device__ __forceinline__ unsigned int ld_acq(const unsigned int* p) {
    unsigned int v;
    asm volatile("ld.acquire.gpu.global.u32 %0, [%1];" : "=r"(v) : "l"(p) : "memory");
    return v;
}
__device__ __forceinline__ float sigmoid_f(float x) {
    return __fdividef(1.0f, 1.0f + __expf(-x));
}
__device__ __forceinline__ float tanh_ap(float x) {
    float y; asm("tanh.approx.f32 %0, %1;" : "=f"(y) : "f"(x)); return y;
}

// partial wait: warp waits for its 4 producer blocks' flags (each on a
// private line; 8-lane broadcast dedupe -> 4 L2 requests per iteration).
// flags are atomically RED-incremented; value t+1 means step t published.
__device__ __forceinline__ void wait4(const unsigned int* base, int w,
                                      unsigned int tgt, int j)
{
    const unsigned int* p = base + (4 * w + (j & 3)) * 32;
    unsigned int v = ld_acq(p);
    while (__any_sync(0xFFFFFFFFu, v < tgt))
        v = ld_acq(p);
    __syncwarp();
}

// ============================================================================
// Phase 1: input projections. Block (0,0,0) zeroes flags; blocks (x<16,0,0)
// seed g_hbuf from h0. Re-done every launch (graph-replay safe).
// ============================================================================
__global__ __launch_bounds__(256) void proj_kernel(
    const float* __restrict__ X,  const float* __restrict__ h0,
    const float* __restrict__ Wf, const float* __restrict__ bf,
    const float* __restrict__ Wh, const float* __restrict__ bh)
{
    if (blockIdx.y == 0 && blockIdx.z == 0) {
        if (blockIdx.x == 0) {
            #pragma unroll
            for (int q = 0; q < (N_GROUPS * 32 * 32) / 256; q++)
                g_flg[threadIdx.x + q * 256] = 0u;
        }
        if (blockIdx.x < 16) {
            const float4* s = (const float4*)&h0[blockIdx.x * 4 * HDIM];
            float4* d = (float4*)&g_hbuf[blockIdx.x * 4 * HDIM];
            d[threadIdx.x]       = s[threadIdx.x];
            d[threadIdx.x + 256] = s[threadIdx.x + 256];
        }
    }

    const float* W  = blockIdx.z ? Wh : Wf;
    const float* bv = blockIdx.z ? bh : bf;
    float* out = blockIdx.z ? g_xh : g_xf;

    __shared__ float As[16][132];
    __shared__ float Bs[16][68];

    const int tid = threadIdx.x;
    const int tx = tid & 15;
    const int ty = tid >> 4;
    const long m0 = (long)blockIdx.x * 128;
    const int  n0 = blockIdx.y * 64;

    u64 acc[4][4];
    #pragma unroll
    for (int p = 0; p < 4; p++)
        #pragma unroll
        for (int c = 0; c < 4; c++) acc[p][c] = 0ull;

    for (int k0 = 0; k0 < IDIM; k0 += 16) {
        #pragma unroll
        for (int q0 = 0; q0 < 2; q0++) {
            int q = tid + q0 * 256;
            int row = q >> 2;
            int kc  = (q & 3) * 4;
            float4 v = *(const float4*)&X[(m0 + row) * IDIM + k0 + kc];
            As[kc+0][row] = v.x; As[kc+1][row] = v.y;
            As[kc+2][row] = v.z; As[kc+3][row] = v.w;
        }
        {
            int row = tid >> 2;
            int kc  = (tid & 3) * 4;
            float4 v = *(const float4*)&W[(n0 + row) * IDIM + k0 + kc];
            Bs[kc+0][row] = v.x; Bs[kc+1][row] = v.y;
            Bs[kc+2][row] = v.z; Bs[kc+3][row] = v.w;
        }
        __syncthreads();

        #pragma unroll
        for (int kk = 0; kk < 16; kk++) {
            float4 a0 = *(const float4*)&As[kk][ty * 8];
            float4 a1 = *(const float4*)&As[kk][ty * 8 + 4];
            float4 b4 = *(const float4*)&Bs[kk][tx * 4];
            u64 a2[4] = { pack2(a0.x, a0.y), pack2(a0.z, a0.w),
                          pack2(a1.x, a1.y), pack2(a1.z, a1.w) };
            u64 bb[4] = { pack2(b4.x, b4.x), pack2(b4.y, b4.y),
                          pack2(b4.z, b4.z), pack2(b4.w, b4.w) };
            #pragma unroll
            for (int p = 0; p < 4; p++)
                #pragma unroll
                for (int c = 0; c < 4; c++)
                    acc[p][c] = ffma2(a2[p], bb[c], acc[p][c]);
        }
        __syncthreads();
    }

    float4 bias4 = *(const float4*)&bv[n0 + tx * 4];
    #pragma unroll
    for (int p = 0; p < 4; p++) {
        float2 c0 = unpack2(acc[p][0]);
        float2 c1 = unpack2(acc[p][1]);
        float2 c2 = unpack2(acc[p][2]);
        float2 c3 = unpack2(acc[p][3]);
        long mlo = m0 + ty * 8 + 2 * p;
        float4 lo = make_float4(c0.x + bias4.x, c1.x + bias4.y,
                                c2.x + bias4.z, c3.x + bias4.w);
        float4 hi = make_float4(c0.y + bias4.x, c1.y + bias4.y,
                                c2.y + bias4.z, c3.y + bias4.w);
        *(float4*)&out[mlo * HDIM + n0 + tx * 4]       = lo;
        *(float4*)&out[(mlo + 1) * HDIM + n0 + tx * 4] = hi;
    }
}

// ============================================================================
// Phase 2: persistent scan (R7 champion body). Sync protocol: per-block
// atomic flags on private lines, block-level release (syncthreads + ONE
// red.release by tid 0), per-warp partial waits on the warp's 4 producer
// blocks (warp w consumes k-slice [128w,+128) = columns of blocks 4w..4w+3).
// ============================================================================
#define WH_STRIDE 132
#define SCAN_SMEM ((128 * WH_STRIDE + 4 * 512 + 512 + 512) * 4)

__global__ void __launch_bounds__(128, 2) scan_kernel(
    const float* __restrict__ h0,
    const float* __restrict__ Whf,
    const float* __restrict__ Whh,
    float* __restrict__ out)
{
    extern __shared__ float smem[];
    float* whs   = smem;                     // 128 slices x 132
    float* srcs  = whs + 128 * WH_STRIDE;    // 4 warps x 512 (warp-private)
    float* partA = srcs + 4 * 512;           // [row][ks][j] 4*4*32
    float* partB = partA + 512;

    const int tid = threadIdx.x;
    const int j   = tid & 31;      // lane = column within block
    const int w   = tid >> 5;      // warp = k-slice index AND finalize row
    const int grp = blockIdx.x >> 4;
    const int blk = blockIdx.x & 15;
    const int j0  = blk * COLS_PER_BLK;
    const int b0  = grp * B_PER_GROUP;
    const int kb  = w * 128;

    unsigned int* flagA = &g_flg[(grp * 32 + 0)  * 32];   // phase A lines
    unsigned int* flagB = &g_flg[(grp * 32 + 16) * 32];   // phase B lines

    // Wf slice -> registers (128 floats = 64 u64)
    u64 wf2[64];
    #pragma unroll
    for (int i = 0; i < 32; i++) {
        float4 v = *(const float4*)&Whf[(j0 + j) * HDIM + kb + 4 * i];
        wf2[2*i] = pack2(v.x, v.y); wf2[2*i+1] = pack2(v.z, v.w);
    }
    // Wh slice -> private SMEM region (thread-local)
    float* wr = &whs[(w * 32 + j) * WH_STRIDE];
    #pragma unroll
    for (int i = 0; i < 32; i++)
        *(float4*)&wr[4 * i] = *(const float4*)&Whh[(j0 + j) * HDIM + kb + 4 * i];

    float hp = h0[(b0 + w) * HDIM + j0 + j];
    __syncthreads();

    float* sb = &srcs[w * 512];
    const long xstep = (long)BATCH * HDIM;
    long xoff = (long)(b0 + w) * HDIM + j0 + j;   // rolling [t,b,col] offset

    float f_reg = 0.0f;

    for (int t = 0; t < T_STEPS; t++) {
        const unsigned int tcur = (unsigned int)(t + 1);
        const float xf_v = __ldcs(&g_xf[xoff]);
        const float xh_v = __ldcs(&g_xh[xoff]);

        // ---- wait for h_{t-1} from this warp's 4 producer blocks ----
        if (t > 0) wait4(flagB, w, tcur - 1u, j);

        // ---- per-warp gather: 4 rows x own k-slice of h ----
        {
            const float4* hb = (const float4*)&g_hbuf[b0 * HDIM + kb];
            float4 v0 = ldcg4(hb + j);
            float4 v1 = ldcg4(hb + 128 + j);
            float4 v2 = ldcg4(hb + 256 + j);
            float4 v3 = ldcg4(hb + 384 + j);
            *(float4*)&sb[        4 * j] = v0;
            *(float4*)&sb[128 +   4 * j] = v1;
            *(float4*)&sb[256 +   4 * j] = v2;
            *(float4*)&sb[384 +   4 * j] = v3;
        }
        __syncwarp();

        // ---- GEMM A (f gate), Wf from registers ----
        {
            u64 a0 = 0ull, a1 = 0ull, a2 = 0ull, a3 = 0ull;
            #pragma unroll
            for (int i = 0; i < 32; i++) {
                u64 wlo = wf2[2*i], whi = wf2[2*i+1];
                float4 x0 = *(const float4*)&sb[        4 * i];
                float4 x1 = *(const float4*)&sb[128 +   4 * i];
                float4 x2 = *(const float4*)&sb[256 +   4 * i];
                float4 x3 = *(const float4*)&sb[384 +   4 * i];
                a0 = ffma2(wlo, pack2(x0.x, x0.y), a0);
                a0 = ffma2(whi, pack2(x0.z, x0.w), a0);
                a1 = ffma2(wlo, pack2(x1.x, x1.y), a1);
                a1 = ffma2(whi, pack2(x1.z, x1.w), a1);
                a2 = ffma2(wlo, pack2(x2.x, x2.y), a2);
                a2 = ffma2(whi, pack2(x2.z, x2.w), a2);
                a3 = ffma2(wlo, pack2(x3.x, x3.y), a3);
                a3 = ffma2(whi, pack2(x3.z, x3.w), a3);
            }
            float2 r0 = unpack2(a0), r1 = unpack2(a1);
            float2 r2 = unpack2(a2), r3 = unpack2(a3);
            partA[(0 * 4 + w) * 32 + j] = r0.x + r0.y;
            partA[(1 * 4 + w) * 32 + j] = r1.x + r1.y;
            partA[(2 * 4 + w) * 32 + j] = r2.x + r2.y;
            partA[(3 * 4 + w) * 32 + j] = r3.x + r3.y;
        }
        __syncthreads();

        // ---- finalize A: warp w owns row w; publish g ----
        {
            float s = xf_v;
            #pragma unroll
            for (int q = 0; q < 4; q++) s += partA[(w * 4 + q) * 32 + j];
            f_reg = sigmoid_f(s);
            g_gbuf[(b0 + w) * HDIM + j0 + j] = f_reg * hp;
        }
        __syncthreads();                     // all warps' g stores done
        if (tid == 0) red_release(&flagA[blk * 32]);   // ONE RED, private line

        // ---- wait for g_t from this warp's 4 producer blocks ----
        wait4(flagA, w, tcur, j);

        // ---- per-warp gather of g ----
        {
            const float4* gb = (const float4*)&g_gbuf[b0 * HDIM + kb];
            float4 v0 = ldcg4(gb + j);
            float4 v1 = ldcg4(gb + 128 + j);
            float4 v2 = ldcg4(gb + 256 + j);
            float4 v3 = ldcg4(gb + 384 + j);
            *(float4*)&sb[        4 * j] = v0;
            *(float4*)&sb[128 +   4 * j] = v1;
            *(float4*)&sb[256 +   4 * j] = v2;
            *(float4*)&sb[384 +   4 * j] = v3;
        }
        __syncwarp();

        // ---- GEMM B (candidate), Wh from SMEM ----
        {
            u64 a0 = 0ull, a1 = 0ull, a2 = 0ull, a3 = 0ull;
            #pragma unroll
            for (int i = 0; i < 32; i++) {
                float4 wv = *(const float4*)&wr[4 * i];
                u64 wlo = pack2(wv.x, wv.y), whi = pack2(wv.z, wv.w);
                float4 x0 = *(const float4*)&sb[        4 * i];
                float4 x1 = *(const float4*)&sb[128 +   4 * i];
                float4 x2 = *(const float4*)&sb[256 +   4 * i];
                float4 x3 = *(const float4*)&sb[384 +   4 * i];
                a0 = ffma2(wlo, pack2(x0.x, x0.y), a0);
                a0 = ffma2(whi, pack2(x0.z, x0.w), a0);
                a1 = ffma2(wlo, pack2(x1.x, x1.y), a1);
                a1 = ffma2(whi, pack2(x1.z, x1.w), a1);
                a2 = ffma2(wlo, pack2(x2.x, x2.y), a2);
                a2 = ffma2(whi, pack2(x2.z, x2.w), a2);
                a3 = ffma2(wlo, pack2(x3.x, x3.y), a3);
                a3 = ffma2(whi, pack2(x3.z, x3.w), a3);
            }
            float2 r0 = unpack2(a0), r1 = unpack2(a1);
            float2 r2 = unpack2(a2), r3 = unpack2(a3);
            partB[(0 * 4 + w) * 32 + j] = r0.x + r0.y;
            partB[(1 * 4 + w) * 32 + j] = r1.x + r1.y;
            partB[(2 * 4 + w) * 32 + j] = r2.x + r2.y;
            partB[(3 * 4 + w) * 32 + j] = r3.x + r3.y;
        }
        __syncthreads();

        // ---- finalize B: blend, emit y and h ----
        {
            float s = xh_v;
            #pragma unroll
            for (int q = 0; q < 4; q++) s += partB[(w * 4 + q) * 32 + j];
            float ht = tanh_ap(s);
            float hn = fmaf(f_reg, ht - hp, hp);        // (1-f)h + f*ht
            __stcs(&out[xoff], hn);
            g_hbuf[(b0 + w) * HDIM + j0 + j] = hn;
            if (t == T_STEPS - 1)
                out[(long)T_STEPS * xstep + (b0 + w) * HDIM + j0 + j] = hn;
            hp = hn;
        }
        __syncthreads();                     // all warps' h stores done
        if (tid == 0) red_release(&flagB[blk * 32]);

        xoff += xstep;
    }
}

// ============================================================================
extern "C" void kernel_launch(void* const* d_in, const int* in_sizes, int n_in,
                              void* d_out, int out_size)
{
    const float* x   = (const float*)d_in[0];
    const float* h0  = (const float*)d_in[1];
    const float* Wxf = (const float*)d_in[2];
    const float* Whf = (const float*)d_in[3];
    const float* bf  = (const float*)d_in[4];
    const float* Wxh = (const float*)d_in[5];
    const float* Whh = (const float*)d_in[6];
    const float* bh  = (const float*)d_in[7];
    float* out = (float*)d_out;

    cudaFuncSetAttribute(scan_kernel,
                         cudaFuncAttributeMaxDynamicSharedMemorySize, SCAN_SMEM);

    dim3 pgrid((T_STEPS * BATCH) / 128, HDIM / 64, 2);
    proj_kernel<<<pgrid, 256>>>(x, h0, Wxf, bf, Wxh, bh);

    scan_kernel<<<N_GROUPS * BLKS_PER_GROUP, 128, SCAN_SMEM>>>(h0, Whf, Whh, out);
}

// round 14
// speedup vs baseline: 2.1394x; 1.0147x over previous
#include <cuda_runtime.h>
#include <cstdint>

#define T_STEPS 2048
#define BATCH   64
#define IDIM    512
#define HDIM    512

#define N_GROUPS 16           // chains of 4 batch rows
#define BLKS_PER_GROUP 16     // column blocks per chain (32 H-cols each)
#define B_PER_GROUP 4
#define COLS_PER_BLK 32

typedef unsigned long long u64;

// ---------------- scratch -----------------------------------------------
__device__ float g_xf[(long)T_STEPS * BATCH * HDIM];
__device__ float g_xh[(long)T_STEPS * BATCH * HDIM];
__device__ float g_hbuf[BATCH * HDIM];
__device__ float g_gbuf[BATCH * HDIM];
// per-block atomic flags, ONE PER 128B LINE (32 u32 stride).
// line index = grp*32 + phase*16 + blk   (phase 0 = A/g, 1 = B/h)
__device__ unsigned int g_flg[N_GROUPS * 32 * 32];

// ---------------- packed f32x2 helpers -----------------------------------
__device__ __forceinline__ u64 pack2(float x, float y) {
    u64 r; asm("mov.b64 %0, {%1, %2};" : "=l"(r) : "f"(x), "f"(y)); return r;
}
__device__ __forceinline__ u64 ffma2(u64 a, u64 b, u64 c) {
    u64 d; asm("fma.rn.f32x2 %0, %1, %2, %3;" : "=l"(d) : "l"(a), "l"(b), "l"(c));
    return d;
}
__device__ __forceinline__ float2 unpack2(u64 a) {
    float2 r; asm("mov.b64 {%0, %1}, %2;" : "=f"(r.x), "=f"(r.y) : "l"(a)); return r;
}
__device__ __forceinline__ float4 ldcg4(const float4* p) {
    float4 v;
    asm volatile("ld.global.cg.v4.f32 {%0,%1,%2,%3}, [%4];"
                 : "=f"(v.x), "=f"(v.y), "=f"(v.z), "=f"(v.w) : "l"(p));
    return v;
}
__device__ __forceinline__ void red_release(unsigned int* p) {
    asm volatile("red.release.gpu.global.add.u32 [%0], 1;" :: "l"(p) : "memory");
}
__device__ __forceinline__ unsigned int ld_acq(const unsigned int* p) {
    unsigned int v;
    asm volatile("ld.acquire.gpu.global.u32 %0, [%1];" : "=r"(v) : "l"(p) : "memory");
    return v;
}
__device__ __forceinline__ float sigmoid_f(float x) {
    return __fdividef(1.0f, 1.0f + __expf(-x));
}
__device__ __forceinline__ float tanh_ap(float x) {
    float y; asm("tanh.approx.f32 %0, %1;" : "=f"(y) : "f"(x)); return y;
}

// partial wait: warp waits for its 2 producer blocks' flags (each on a
// private line). Flags are RED-incremented; value t+1 means step t published.
__device__ __forceinline__ void wait2(const unsigned int* base, int w,
                                      unsigned int tgt, int j)
{
    const unsigned int* p = base + (2 * w + (j & 1)) * 32;
    unsigned int v = ld_acq(p);
    while (__any_sync(0xFFFFFFFFu, v < tgt))
        v = ld_acq(p);
    __syncwarp();
}

// ============================================================================
// Phase 1: input projections. Block (0,0,0) zeroes flags; blocks (x<16,0,0)
// seed g_hbuf from h0. Re-done every launch (graph-replay safe).
// ============================================================================
__global__ __launch_bounds__(256) void proj_kernel(
    const float* __restrict__ X,  const float* __restrict__ h0,
    const float* __restrict__ Wf, const float* __restrict__ bf,
    const float* __restrict__ Wh, const float* __restrict__ bh)
{
    if (blockIdx.y == 0 && blockIdx.z == 0) {
        if (blockIdx.x == 0) {
            #pragma unroll
            for (int q = 0; q < (N_GROUPS * 32 * 32) / 256; q++)
                g_flg[threadIdx.x + q * 256] = 0u;
        }
        if (blockIdx.x < 16) {
            const float4* s = (const float4*)&h0[blockIdx.x * 4 * HDIM];
            float4* d = (float4*)&g_hbuf[blockIdx.x * 4 * HDIM];
            d[threadIdx.x]       = s[threadIdx.x];
            d[threadIdx.x + 256] = s[threadIdx.x + 256];
        }
    }

    const float* W  = blockIdx.z ? Wh : Wf;
    const float* bv = blockIdx.z ? bh : bf;
    float* out = blockIdx.z ? g_xh : g_xf;

    __shared__ float As[16][132];
    __shared__ float Bs[16][68];

    const int tid = threadIdx.x;
    const int tx = tid & 15;
    const int ty = tid >> 4;
    const long m0 = (long)blockIdx.x * 128;
    const int  n0 = blockIdx.y * 64;

    u64 acc[4][4];
    #pragma unroll
    for (int p = 0; p < 4; p++)
        #pragma unroll
        for (int c = 0; c < 4; c++) acc[p][c] = 0ull;

    for (int k0 = 0; k0 < IDIM; k0 += 16) {
        #pragma unroll
        for (int q0 = 0; q0 < 2; q0++) {
            int q = tid + q0 * 256;
            int row = q >> 2;
            int kc  = (q & 3) * 4;
            float4 v = *(const float4*)&X[(m0 + row) * IDIM + k0 + kc];
            As[kc+0][row] = v.x; As[kc+1][row] = v.y;
            As[kc+2][row] = v.z; As[kc+3][row] = v.w;
        }
        {
            int row = tid >> 2;
            int kc  = (tid & 3) * 4;
            float4 v = *(const float4*)&W[(n0 + row) * IDIM + k0 + kc];
            Bs[kc+0][row] = v.x; Bs[kc+1][row] = v.y;
            Bs[kc+2][row] = v.z; Bs[kc+3][row] = v.w;
        }
        __syncthreads();

        #pragma unroll
        for (int kk = 0; kk < 16; kk++) {
            float4 a0 = *(const float4*)&As[kk][ty * 8];
            float4 a1 = *(const float4*)&As[kk][ty * 8 + 4];
            float4 b4 = *(const float4*)&Bs[kk][tx * 4];
            u64 a2[4] = { pack2(a0.x, a0.y), pack2(a0.z, a0.w),
                          pack2(a1.x, a1.y), pack2(a1.z, a1.w) };
            u64 bb[4] = { pack2(b4.x, b4.x), pack2(b4.y, b4.y),
                          pack2(b4.z, b4.z), pack2(b4.w, b4.w) };
            #pragma unroll
            for (int p = 0; p < 4; p++)
                #pragma unroll
                for (int c = 0; c < 4; c++)
                    acc[p][c] = ffma2(a2[p], bb[c], acc[p][c]);
        }
        __syncthreads();
    }

    float4 bias4 = *(const float4*)&bv[n0 + tx * 4];
    #pragma unroll
    for (int p = 0; p < 4; p++) {
        float2 c0 = unpack2(acc[p][0]);
        float2 c1 = unpack2(acc[p][1]);
        float2 c2 = unpack2(acc[p][2]);
        float2 c3 = unpack2(acc[p][3]);
        long mlo = m0 + ty * 8 + 2 * p;
        float4 lo = make_float4(c0.x + bias4.x, c1.x + bias4.y,
                                c2.x + bias4.z, c3.x + bias4.w);
        float4 hi = make_float4(c0.y + bias4.x, c1.y + bias4.y,
                                c2.y + bias4.z, c3.y + bias4.w);
        *(float4*)&out[mlo * HDIM + n0 + tx * 4]       = lo;
        *(float4*)&out[(mlo + 1) * HDIM + n0 + tx * 4] = hi;
    }
}

// ============================================================================
// Phase 2: persistent scan. 256 blocks x 256 threads (8 warps), 2/SM.
// Chain = 4 batch rows x 16 column blocks. Warp w owns 64-wide k-slice
// [w*64,+64) (produced by blocks 2w,2w+1 -> wait2 partial waits). Warps
// 0-3 additionally own finalize row w. Wf slice register-resident (64 f);
// Wh slice in conflict-free SMEM. Protocol identical to R13 champion:
// private-line RED flags, block-level release, lane-duplicated polls.
// ============================================================================
#define WH_STRIDE 68
#define SCAN_SMEM ((256 * WH_STRIDE + 8 * 256 + 1024 + 1024) * 4)

__global__ void __launch_bounds__(256, 2) scan_kernel(
    const float* __restrict__ h0,
    const float* __restrict__ Whf,
    const float* __restrict__ Whh,
    float* __restrict__ out)
{
    extern __shared__ float smem[];
    float* whs   = smem;                     // 256 slices x 68
    float* srcs  = whs + 256 * WH_STRIDE;    // 8 warps x (4 rows x 64)
    float* partA = srcs + 8 * 256;           // [row][ks 0..7][j] 4*8*32
    float* partB = partA + 1024;

    const int tid = threadIdx.x;
    const int j   = tid & 31;      // lane = column within block
    const int w   = tid >> 5;      // warp = k-slice index (0..7)
    const int grp = blockIdx.x >> 4;
    const int blk = blockIdx.x & 15;
    const int j0  = blk * COLS_PER_BLK;
    const int b0  = grp * B_PER_GROUP;
    const int kb  = w * 64;
    const int frow = b0 + (w & 3);           // clamped row (used by w<4 only)

    unsigned int* flagA = &g_flg[(grp * 32 + 0)  * 32];   // phase A lines
    unsigned int* flagB = &g_flg[(grp * 32 + 16) * 32];   // phase B lines

    // Wf slice -> registers (64 floats = 32 u64)
    u64 wf2[32];
    #pragma unroll
    for (int i = 0; i < 16; i++) {
        float4 v = *(const float4*)&Whf[(j0 + j) * HDIM + kb + 4 * i];
        wf2[2*i] = pack2(v.x, v.y); wf2[2*i+1] = pack2(v.z, v.w);
    }
    // Wh slice -> private SMEM region (thread-local, 64 floats)
    float* wr = &whs[tid * WH_STRIDE];
    #pragma unroll
    for (int i = 0; i < 16; i++)
        *(float4*)&wr[4 * i] = *(const float4*)&Whh[(j0 + j) * HDIM + kb + 4 * i];

    float hp = (w < 4) ? h0[frow * HDIM + j0 + j] : 0.0f;
    __syncthreads();

    float* sb = &srcs[w * 256];              // warp-private: 4 rows x 64
    const long xstep = (long)BATCH * HDIM;
    long xoff = (long)frow * HDIM + j0 + j;  // rolling [t,row,col] offset

    // gather lane mapping: 64 float4 over 32 lanes, 2 each
    const int gr0 = j >> 4, gc0 = j & 15;          // idx = j
    const int gr1 = (j + 32) >> 4, gc1 = j & 15;   // idx = j + 32

    float f_reg = 0.0f;

    for (int t = 0; t < T_STEPS; t++) {
        const unsigned int tcur = (unsigned int)(t + 1);
        const float xf_v = (w < 4) ? __ldcs(&g_xf[xoff]) : 0.0f;
        const float xh_v = (w < 4) ? __ldcs(&g_xh[xoff]) : 0.0f;

        // ---- wait for h_{t-1} from this warp's 2 producer blocks ----
        if (t > 0) wait2(flagB, w, tcur - 1u, j);

        // ---- per-warp gather: 4 rows x own 64-wide k-slice of h ----
        {
            const float* hb = &g_hbuf[b0 * HDIM + kb];
            float4 v0 = ldcg4((const float4*)(hb + gr0 * HDIM) + gc0);
            float4 v1 = ldcg4((const float4*)(hb + gr1 * HDIM) + gc1);
            *(float4*)&sb[gr0 * 64 + 4 * gc0] = v0;
            *(float4*)&sb[gr1 * 64 + 4 * gc1] = v1;
        }
        __syncwarp();

        // ---- GEMM A (f gate), Wf from registers: 4 rows x 64 k ----
        {
            u64 a0 = 0ull, a1 = 0ull, a2 = 0ull, a3 = 0ull;
            #pragma unroll
            for (int i = 0; i < 16; i++) {
                u64 wlo = wf2[2*i], whi = wf2[2*i+1];
                float4 x0 = *(const float4*)&sb[        4 * i];
                float4 x1 = *(const float4*)&sb[ 64 +   4 * i];
                float4 x2 = *(const float4*)&sb[128 +   4 * i];
                float4 x3 = *(const float4*)&sb[192 +   4 * i];
                a0 = ffma2(wlo, pack2(x0.x, x0.y), a0);
                a0 = ffma2(whi, pack2(x0.z, x0.w), a0);
                a1 = ffma2(wlo, pack2(x1.x, x1.y), a1);
                a1 = ffma2(whi, pack2(x1.z, x1.w), a1);
                a2 = ffma2(wlo, pack2(x2.x, x2.y), a2);
                a2 = ffma2(whi, pack2(x2.z, x2.w), a2);
                a3 = ffma2(wlo, pack2(x3.x, x3.y), a3);
                a3 = ffma2(whi, pack2(x3.z, x3.w), a3);
            }
            float2 r0 = unpack2(a0), r1 = unpack2(a1);
            float2 r2 = unpack2(a2), r3 = unpack2(a3);
            partA[(0 * 8 + w) * 32 + j] = r0.x + r0.y;
            partA[(1 * 8 + w) * 32 + j] = r1.x + r1.y;
            partA[(2 * 8 + w) * 32 + j] = r2.x + r2.y;
            partA[(3 * 8 + w) * 32 + j] = r3.x + r3.y;
        }
        __syncthreads();

        // ---- finalize A: warps 0-3 own rows 0-3; publish g ----
        if (w < 4) {
            float s = xf_v;
            #pragma unroll
            for (int q = 0; q < 8; q++) s += partA[(w * 8 + q) * 32 + j];
            f_reg = sigmoid_f(s);
            g_gbuf[frow * HDIM + j0 + j] = f_reg * hp;
        }
        __syncthreads();                     // all g stores of the block done
        if (tid == 0) red_release(&flagA[blk * 32]);   // ONE RED, private line

        // ---- wait for g_t from this warp's 2 producer blocks ----
        wait2(flagA, w, tcur, j);

        // ---- per-warp gather of g ----
        {
            const float* gb = &g_gbuf[b0 * HDIM + kb];
            float4 v0 = ldcg4((const float4*)(gb + gr0 * HDIM) + gc0);
            float4 v1 = ldcg4((const float4*)(gb + gr1 * HDIM) + gc1);
            *(float4*)&sb[gr0 * 64 + 4 * gc0] = v0;
            *(float4*)&sb[gr1 * 64 + 4 * gc1] = v1;
        }
        __syncwarp();

        // ---- GEMM B (candidate), Wh from SMEM ----
        {
            u64 a0 = 0ull, a1 = 0ull, a2 = 0ull, a3 = 0ull;
            #pragma unroll
            for (int i = 0; i < 16; i++) {
                float4 wv = *(const float4*)&wr[4 * i];
                u64 wlo = pack2(wv.x, wv.y), whi = pack2(wv.z, wv.w);
                float4 x0 = *(const float4*)&sb[        4 * i];
                float4 x1 = *(const float4*)&sb[ 64 +   4 * i];
                float4 x2 = *(const float4*)&sb[128 +   4 * i];
                float4 x3 = *(const float4*)&sb[192 +   4 * i];
                a0 = ffma2(wlo, pack2(x0.x, x0.y), a0);
                a0 = ffma2(whi, pack2(x0.z, x0.w), a0);
                a1 = ffma2(wlo, pack2(x1.x, x1.y), a1);
                a1 = ffma2(whi, pack2(x1.z, x1.w), a1);
                a2 = ffma2(wlo, pack2(x2.x, x2.y), a2);
                a2 = ffma2(whi, pack2(x2.z, x2.w), a2);
                a3 = ffma2(wlo, pack2(x3.x, x3.y), a3);
                a3 = ffma2(whi, pack2(x3.z, x3.w), a3);
            }
            float2 r0 = unpack2(a0), r1 = unpack2(a1);
            float2 r2 = unpack2(a2), r3 = unpack2(a3);
            partB[(0 * 8 + w) * 32 + j] = r0.x + r0.y;
            partB[(1 * 8 + w) * 32 + j] = r1.x + r1.y;
            partB[(2 * 8 + w) * 32 + j] = r2.x + r2.y;
            partB[(3 * 8 + w) * 32 + j] = r3.x + r3.y;
        }
        __syncthreads();

        // ---- finalize B: blend, emit y and h (warps 0-3) ----
        if (w < 4) {
            float s = xh_v;
            #pragma unroll
            for (int q = 0; q < 8; q++) s += partB[(w * 8 + q) * 32 + j];
            float ht = tanh_ap(s);
            float hn = fmaf(f_reg, ht - hp, hp);        // (1-f)h + f*ht
            __stcs(&out[xoff], hn);
            g_hbuf[frow * HDIM + j0 + j] = hn;
            if (t == T_STEPS - 1)
                out[(long)T_STEPS * xstep + frow * HDIM + j0 + j] = hn;
            hp = hn;
        }
        __syncthreads();                     // all h stores of the block done
        if (tid == 0) red_release(&flagB[blk * 32]);

        xoff += xstep;
    }
}

// ============================================================================
extern "C" void kernel_launch(void* const* d_in, const int* in_sizes, int n_in,
                              void* d_out, int out_size)
{
    const float* x   = (const float*)d_in[0];
    const float* h0  = (const float*)d_in[1];
    const float* Wxf = (const float*)d_in[2];
    const float* Whf = (const float*)d_in[3];
    const float* bf  = (const float*)d_in[4];
    const float* Wxh = (const float*)d_in[5];
    const float* Whh = (const float*)d_in[6];
    const float* bh  = (const float*)d_in[7];
    float* out = (float*)d_out;

    cudaFuncSetAttribute(scan_kernel,
                         cudaFuncAttributeMaxDynamicSharedMemorySize, SCAN_SMEM);

    dim3 pgrid((T_STEPS * BATCH) / 128, HDIM / 64, 2);
    proj_kernel<<<pgrid, 256>>>(x, h0, Wxf, bf, Wxh, bh);

    scan_kernel<<<N_GROUPS * BLKS_PER_GROUP, 256, SCAN_SMEM>>>(h0, Whf, Whh, out);
}

// round 15
// speedup vs baseline: 2.2631x; 1.0578x over previous
#include <cuda_runtime.h>
#include <cstdint>

#define T_STEPS 2048
#define BATCH   64
#define IDIM    512
#define HDIM    512

#define N_GROUPS 16           // chains of 4 batch rows
#define BLKS_PER_GROUP 16     // column blocks per chain (32 H-cols each)
#define B_PER_GROUP 4
#define COLS_PER_BLK 32

#define SCAN_BLOCKS 256
#define WORKER_BLOCKS 40
#define NTILES 1024           // m-tiles (128 rows = 2 timesteps each)
#define NTILES_PREFIX 512     // m-tiles done by scan blocks up front
#define JOBS_PER_TILE 16      // 8 n-tiles x 2 (xf/xh)
#define JOBS_TOTAL   (NTILES * JOBS_PER_TILE)
#define JOBS_PREFIX  (NTILES_PREFIX * JOBS_PER_TILE)

typedef unsigned long long u64;

// ---------------- scratch -----------------------------------------------
__device__ float g_xf[(long)T_STEPS * BATCH * HDIM];
__device__ float g_xh[(long)T_STEPS * BATCH * HDIM];
__device__ float g_hbuf[BATCH * HDIM];
__device__ float g_gbuf[BATCH * HDIM];
// scan flags: per-block atomic flags, one per 128B line
__device__ unsigned int g_flg[N_GROUPS * 32 * 32];
// proj m-tile flags: one per 128B line; value 16 == tile ready
__device__ unsigned int g_mflg[NTILES * 32];

// ---------------- packed f32x2 helpers -----------------------------------
__device__ __forceinline__ u64 pack2(float x, float y) {
    u64 r; asm("mov.b64 %0, {%1, %2};" : "=l"(r) : "f"(x), "f"(y)); return r;
}
__device__ __forceinline__ u64 ffma2(u64 a, u64 b, u64 c) {
    u64 d; asm("fma.rn.f32x2 %0, %1, %2, %3;" : "=l"(d) : "l"(a), "l"(b), "l"(c));
    return d;
}
__device__ __forceinline__ float2 unpack2(u64 a) {
    float2 r; asm("mov.b64 {%0, %1}, %2;" : "=f"(r.x), "=f"(r.y) : "l"(a)); return r;
}
__device__ __forceinline__ float4 ldcg4(const float4* p) {
    float4 v;
    asm volatile("ld.global.cg.v4.f32 {%0,%1,%2,%3}, [%4];"
                 : "=f"(v.x), "=f"(v.y), "=f"(v.z), "=f"(v.w) : "l"(p));
    return v;
}
__device__ __forceinline__ void red_release(unsigned int* p) {
    asm volatile("red.release.gpu.global.add.u32 [%0], 1;" :: "l"(p) : "memory");
}
__device__ __forceinline__ unsigned int ld_acq(const unsigned int* p) {
    unsigned int v;
    asm volatile("ld.acquire.gpu.global.u32 %0, [%1];" : "=r"(v) : "l"(p) : "memory");
    return v;
}
__device__ __forceinline__ float sigmoid_f(float x) {
    return __fdividef(1.0f, 1.0f + __expf(-x));
}
__device__ __forceinline__ float tanh_ap(float x) {
    float y; asm("tanh.approx.f32 %0, %1;" : "=f"(y) : "f"(x)); return y;
}

// partial wait: warp waits for its 2 producer blocks' flags
__device__ __forceinline__ void wait2(const unsigned int* base, int w,
                                      unsigned int tgt, int j)
{
    const unsigned int* p = base + (2 * w + (j & 1)) * 32;
    unsigned int v = ld_acq(p);
    while (__any_sync(0xFFFFFFFFu, v < tgt))
        v = ld_acq(p);
    __syncwarp();
}

// ============================================================================
// init: zero all flags (re-done every launch; graph-replay safe)
// ============================================================================
__global__ void init_kernel() {
    int i = blockIdx.x * 256 + threadIdx.x;
    if (i < N_GROUPS * 32 * 32) g_flg[i] = 0u;
    if (i < NTILES * 32) g_mflg[i] = 0u;
}

// ============================================================================
// one projection tile job: 128 rows x 64 cols x K=512 of xf or xh.
// job = (m_tile << 4) | (n_tile << 1) | z.  Uses smem[0 .. 3200) floats.
// Publishes by RED on the m-tile flag (16 jobs per tile).
// ============================================================================
__device__ void proj_tile(
    int job, float* smem,
    const float* __restrict__ X,
    const float* __restrict__ Wxf, const float* __restrict__ bf,
    const float* __restrict__ Wxh, const float* __restrict__ bh)
{
    float* As = smem;              // [16][132]
    float* Bs = smem + 16 * 132;   // [16][68]

    const int m  = job >> 4;
    const int n0 = ((job >> 1) & 7) * 64;
    const int z  = job & 1;
    const float* W  = z ? Wxh : Wxf;
    const float* bv = z ? bh : bf;
    float* outp = z ? g_xh : g_xf;
    const long m0 = (long)m * 128;

    const int tid = threadIdx.x;
    const int tx = tid & 15;
    const int ty = tid >> 4;

    u64 acc[4][4];
    #pragma unroll
    for (int p = 0; p < 4; p++)
        #pragma unroll
        for (int c = 0; c < 4; c++) acc[p][c] = 0ull;

    for (int k0 = 0; k0 < IDIM; k0 += 16) {
        #pragma unroll
        for (int q0 = 0; q0 < 2; q0++) {
            int q = tid + q0 * 256;
            int row = q >> 2;
            int kc  = (q & 3) * 4;
            float4 v = *(const float4*)&X[(m0 + row) * IDIM + k0 + kc];
            As[(kc+0) * 132 + row] = v.x; As[(kc+1) * 132 + row] = v.y;
            As[(kc+2) * 132 + row] = v.z; As[(kc+3) * 132 + row] = v.w;
        }
        {
            int row = tid >> 2;
            int kc  = (tid & 3) * 4;
            float4 v = *(const float4*)&W[(n0 + row) * IDIM + k0 + kc];
            Bs[(kc+0) * 68 + row] = v.x; Bs[(kc+1) * 68 + row] = v.y;
            Bs[(kc+2) * 68 + row] = v.z; Bs[(kc+3) * 68 + row] = v.w;
        }
        __syncthreads();

        #pragma unroll
        for (int kk = 0; kk < 16; kk++) {
            float4 a0 = *(const float4*)&As[kk * 132 + ty * 8];
            float4 a1 = *(const float4*)&As[kk * 132 + ty * 8 + 4];
            float4 b4 = *(const float4*)&Bs[kk * 68 + tx * 4];
            u64 a2[4] = { pack2(a0.x, a0.y), pack2(a0.z, a0.w),
                          pack2(a1.x, a1.y), pack2(a1.z, a1.w) };
            u64 bb[4] = { pack2(b4.x, b4.x), pack2(b4.y, b4.y),
                          pack2(b4.z, b4.z), pack2(b4.w, b4.w) };
            #pragma unroll
            for (int p = 0; p < 4; p++)
                #pragma unroll
                for (int c = 0; c < 4; c++)
                    acc[p][c] = ffma2(a2[p], bb[c], acc[p][c]);
        }
        __syncthreads();
    }

    float4 bias4 = *(const float4*)&bv[n0 + tx * 4];
    #pragma unroll
    for (int p = 0; p < 4; p++) {
        float2 c0 = unpack2(acc[p][0]);
        float2 c1 = unpack2(acc[p][1]);
        float2 c2 = unpack2(acc[p][2]);
        float2 c3 = unpack2(acc[p][3]);
        long mlo = m0 + ty * 8 + 2 * p;
        float4 lo = make_float4(c0.x + bias4.x, c1.x + bias4.y,
                                c2.x + bias4.z, c3.x + bias4.w);
        float4 hi = make_float4(c0.y + bias4.x, c1.y + bias4.y,
                                c2.y + bias4.z, c3.y + bias4.w);
        *(float4*)&outp[mlo * HDIM + n0 + tx * 4]       = lo;
        *(float4*)&outp[(mlo + 1) * HDIM + n0 + tx * 4] = hi;
    }
    __syncthreads();                      // all stores done before publish
    if (tid == 0) red_release(&g_mflg[m * 32]);
}

// ============================================================================
// Fused kernel. Blocks 0..255: proj prefix (m-tiles [0,512)) then scan.
// Blocks 256..295: workers producing m-tiles [512,1024) concurrently.
// Scan body = R14 champion (8 warps, wait2, private-line RED flags), plus a
// per-step m-tile readiness wait before consuming xf/xh, and t=0 h from h0.
// ============================================================================
#define WH_STRIDE 68
#define SCAN_SMEM ((256 * WH_STRIDE + 8 * 256 + 1024 + 1024) * 4)

__global__ void __launch_bounds__(256, 2) fused_kernel(
    const float* __restrict__ X,
    const float* __restrict__ h0,
    const float* __restrict__ Wxf, const float* __restrict__ bf,
    const float* __restrict__ Wxh, const float* __restrict__ bh,
    const float* __restrict__ Whf,
    const float* __restrict__ Whh,
    float* __restrict__ out)
{
    extern __shared__ float smem[];

    // ---------------- worker blocks: produce m-tiles [512,1024) ----------
    if (blockIdx.x >= SCAN_BLOCKS) {
        for (int job = JOBS_PREFIX + (blockIdx.x - SCAN_BLOCKS);
             job < JOBS_TOTAL; job += WORKER_BLOCKS)
            proj_tile(job, smem, X, Wxf, bf, Wxh, bh);
        return;
    }

    // ---------------- scan blocks: prefix proj (m-tiles [0,512)) ---------
    for (int job = blockIdx.x; job < JOBS_PREFIX; job += SCAN_BLOCKS)
        proj_tile(job, smem, X, Wxf, bf, Wxh, bh);
    __syncthreads();

    // ---------------- scan ------------------------------------------------
    float* whs   = smem;                     // 256 slices x 68
    float* srcs  = whs + 256 * WH_STRIDE;    // 8 warps x (4 rows x 64)
    float* partA = srcs + 8 * 256;           // [row][ks 0..7][j] 4*8*32
    float* partB = partA + 1024;

    const int tid = threadIdx.x;
    const int j   = tid & 31;
    const int w   = tid >> 5;
    const int grp = blockIdx.x >> 4;
    const int blk = blockIdx.x & 15;
    const int j0  = blk * COLS_PER_BLK;
    const int b0  = grp * B_PER_GROUP;
    const int kb  = w * 64;
    const int frow = b0 + (w & 3);

    unsigned int* flagA = &g_flg[(grp * 32 + 0)  * 32];
    unsigned int* flagB = &g_flg[(grp * 32 + 16) * 32];

    // Wf slice -> registers (64 floats = 32 u64)
    u64 wf2[32];
    #pragma unroll
    for (int i = 0; i < 16; i++) {
        float4 v = *(const float4*)&Whf[(j0 + j) * HDIM + kb + 4 * i];
        wf2[2*i] = pack2(v.x, v.y); wf2[2*i+1] = pack2(v.z, v.w);
    }
    // Wh slice -> private SMEM region (thread-local, 64 floats)
    float* wr = &whs[tid * WH_STRIDE];
    #pragma unroll
    for (int i = 0; i < 16; i++)
        *(float4*)&wr[4 * i] = *(const float4*)&Whh[(j0 + j) * HDIM + kb + 4 * i];

    float hp = (w < 4) ? h0[frow * HDIM + j0 + j] : 0.0f;
    __syncthreads();

    float* sb = &srcs[w * 256];
    const long xstep = (long)BATCH * HDIM;
    long xoff = (long)frow * HDIM + j0 + j;

    const int gr0 = j >> 4, gc0 = j & 15;
    const int gr1 = (j + 32) >> 4, gc1 = j & 15;

    float f_reg = 0.0f;

    for (int t = 0; t < T_STEPS; t++) {
        const unsigned int tcur = (unsigned int)(t + 1);

        // ---- m-tile readiness + xf/xh loads (consumer warps only) ----
        float xf_v = 0.0f, xh_v = 0.0f;
        if (w < 4) {
            if (j == 0) {
                const unsigned int* mp = &g_mflg[(t >> 1) * 32];
                while (ld_acq(mp) < (unsigned int)JOBS_PER_TILE) { }
            }
            __syncwarp();
            xf_v = __ldcs(&g_xf[xoff]);
            xh_v = __ldcs(&g_xh[xoff]);
        }

        // ---- wait for h_{t-1} from this warp's 2 producer blocks ----
        if (t > 0) wait2(flagB, w, tcur - 1u, j);

        // ---- per-warp gather: 4 rows x own 64-wide k-slice of h ----
        {
            const float* hb = (t == 0) ? &h0[b0 * HDIM + kb]
                                       : &g_hbuf[b0 * HDIM + kb];
            float4 v0 = ldcg4((const float4*)(hb + gr0 * HDIM) + gc0);
            float4 v1 = ldcg4((const float4*)(hb + gr1 * HDIM) + gc1);
            *(float4*)&sb[gr0 * 64 + 4 * gc0] = v0;
            *(float4*)&sb[gr1 * 64 + 4 * gc1] = v1;
        }
        __syncwarp();

        // ---- GEMM A (f gate), Wf from registers: 4 rows x 64 k ----
        {
            u64 a0 = 0ull, a1 = 0ull, a2 = 0ull, a3 = 0ull;
            #pragma unroll
            for (int i = 0; i < 16; i++) {
                u64 wlo = wf2[2*i], whi = wf2[2*i+1];
                float4 x0 = *(const float4*)&sb[        4 * i];
                float4 x1 = *(const float4*)&sb[ 64 +   4 * i];
                float4 x2 = *(const float4*)&sb[128 +   4 * i];
                float4 x3 = *(const float4*)&sb[192 +   4 * i];
                a0 = ffma2(wlo, pack2(x0.x, x0.y), a0);
                a0 = ffma2(whi, pack2(x0.z, x0.w), a0);
                a1 = ffma2(wlo, pack2(x1.x, x1.y), a1);
                a1 = ffma2(whi, pack2(x1.z, x1.w), a1);
                a2 = ffma2(wlo, pack2(x2.x, x2.y), a2);
                a2 = ffma2(whi, pack2(x2.z, x2.w), a2);
                a3 = ffma2(wlo, pack2(x3.x, x3.y), a3);
                a3 = ffma2(whi, pack2(x3.z, x3.w), a3);
            }
            float2 r0 = unpack2(a0), r1 = unpack2(a1);
            float2 r2 = unpack2(a2), r3 = unpack2(a3);
            partA[(0 * 8 + w) * 32 + j] = r0.x + r0.y;
            partA[(1 * 8 + w) * 32 + j] = r1.x + r1.y;
            partA[(2 * 8 + w) * 32 + j] = r2.x + r2.y;
            partA[(3 * 8 + w) * 32 + j] = r3.x + r3.y;
        }
        __syncthreads();

        // ---- finalize A: warps 0-3 own rows 0-3; publish g ----
        if (w < 4) {
            float s = xf_v;
            #pragma unroll
            for (int q = 0; q < 8; q++) s += partA[(w * 8 + q) * 32 + j];
            f_reg = sigmoid_f(s);
            g_gbuf[frow * HDIM + j0 + j] = f_reg * hp;
        }
        __syncthreads();
        if (tid == 0) red_release(&flagA[blk * 32]);

        // ---- wait for g_t from this warp's 2 producer blocks ----
        wait2(flagA, w, tcur, j);

        // ---- per-warp gather of g ----
        {
            const float* gb = &g_gbuf[b0 * HDIM + kb];
            float4 v0 = ldcg4((const float4*)(gb + gr0 * HDIM) + gc0);
            float4 v1 = ldcg4((const float4*)(gb + gr1 * HDIM) + gc1);
            *(float4*)&sb[gr0 * 64 + 4 * gc0] = v0;
            *(float4*)&sb[gr1 * 64 + 4 * gc1] = v1;
        }
        __syncwarp();

        // ---- GEMM B (candidate), Wh from SMEM ----
        {
            u64 a0 = 0ull, a1 = 0ull, a2 = 0ull, a3 = 0ull;
            #pragma unroll
            for (int i = 0; i < 16; i++) {
                float4 wv = *(const float4*)&wr[4 * i];
                u64 wlo = pack2(wv.x, wv.y), whi = pack2(wv.z, wv.w);
                float4 x0 = *(const float4*)&sb[        4 * i];
                float4 x1 = *(const float4*)&sb[ 64 +   4 * i];
                float4 x2 = *(const float4*)&sb[128 +   4 * i];
                float4 x3 = *(const float4*)&sb[192 +   4 * i];
                a0 = ffma2(wlo, pack2(x0.x, x0.y), a0);
                a0 = ffma2(whi, pack2(x0.z, x0.w), a0);
                a1 = ffma2(wlo, pack2(x1.x, x1.y), a1);
                a1 = ffma2(whi, pack2(x1.z, x1.w), a1);
                a2 = ffma2(wlo, pack2(x2.x, x2.y), a2);
                a2 = ffma2(whi, pack2(x2.z, x2.w), a2);
                a3 = ffma2(wlo, pack2(x3.x, x3.y), a3);
                a3 = ffma2(whi, pack2(x3.z, x3.w), a3);
            }
            float2 r0 = unpack2(a0), r1 = unpack2(a1);
            float2 r2 = unpack2(a2), r3 = unpack2(a3);
            partB[(0 * 8 + w) * 32 + j] = r0.x + r0.y;
            partB[(1 * 8 + w) * 32 + j] = r1.x + r1.y;
            partB[(2 * 8 + w) * 32 + j] = r2.x + r2.y;
            partB[(3 * 8 + w) * 32 + j] = r3.x + r3.y;
        }
        __syncthreads();

        // ---- finalize B: blend, emit y and h (warps 0-3) ----
        if (w < 4) {
            float s = xh_v;
            #pragma unroll
            for (int q = 0; q < 8; q++) s += partB[(w * 8 + q) * 32 + j];
            float ht = tanh_ap(s);
            float hn = fmaf(f_reg, ht - hp, hp);        // (1-f)h + f*ht
            __stcs(&out[xoff], hn);
            g_hbuf[frow * HDIM + j0 + j] = hn;
            if (t == T_STEPS - 1)
                out[(long)T_STEPS * xstep + frow * HDIM + j0 + j] = hn;
            hp = hn;
        }
        __syncthreads();
        if (tid == 0) red_release(&flagB[blk * 32]);

        xoff += xstep;
    }
}

// ============================================================================
extern "C" void kernel_launch(void* const* d_in, const int* in_sizes, int n_in,
                              void* d_out, int out_size)
{
    const float* x   = (const float*)d_in[0];
    const float* h0  = (const float*)d_in[1];
    const float* Wxf = (const float*)d_in[2];
    const float* Whf = (const float*)d_in[3];
    const float* bf  = (const float*)d_in[4];
    const float* Wxh = (const float*)d_in[5];
    const float* Whh = (const float*)d_in[6];
    const float* bh  = (const float*)d_in[7];
    float* out = (float*)d_out;

    cudaFuncSetAttribute(fused_kernel,
                         cudaFuncAttributeMaxDynamicSharedMemorySize, SCAN_SMEM);

    // zero all flags (both arrays) — 49152 words
    init_kernel<<<192, 256>>>();

    fused_kernel<<<SCAN_BLOCKS + WORKER_BLOCKS, 256, SCAN_SMEM>>>(
        x, h0, Wxf, bf, Wxh, bh, Whf, Whh, out);
}